// round 1
// baseline (speedup 1.0000x reference)
#include <cuda_runtime.h>
#include <cstdint>

// ============================================================================
// CISSVAE forward on GB300.
// Strategy: counting-sort rows by cluster -> all layers run in permuted row
// order -> per-cluster layers become dense segment GEMMs. One templated
// tf32 mma.sync GEMM (128x128x32 tiles) with fused epilogues.
// ============================================================================

#define BB 16384
#define NC 8
#define MAXT 136   // max M tiles: BB/128 + NC

__device__ float g_bufA[BB * 1024];
__device__ float g_bufB[BB * 1024];
__device__ int   g_perm[BB];
__device__ int   g_cursor[NC];
__device__ int4  g_tiles[MAXT];   // {rowStart, rows, cluster, pad}
__device__ int   g_numTiles;

// ---------------------------------------------------------------------------
// Setup: histogram labels, build segment starts, tile descriptors, cursors.
// ---------------------------------------------------------------------------
__global__ void k_setup(const int* __restrict__ labels) {
    __shared__ int cnt[NC];
    int t = threadIdx.x;
    if (t < NC) cnt[t] = 0;
    __syncthreads();
    int loc[NC];
#pragma unroll
    for (int c = 0; c < NC; c++) loc[c] = 0;
    for (int i = t; i < BB; i += blockDim.x) {
        int v = labels[i];
#pragma unroll
        for (int c = 0; c < NC; c++) loc[c] += (v == c);
    }
#pragma unroll
    for (int c = 0; c < NC; c++)
        if (loc[c]) atomicAdd(&cnt[c], loc[c]);
    __syncthreads();
    if (t == 0) {
        int start = 0, nt = 0;
        for (int c = 0; c < NC; c++) {
            g_cursor[c] = start;
            int n = cnt[c];
            for (int off = 0; off < n; off += 128) {
                g_tiles[nt] = make_int4(start + off, min(128, n - off), c, 0);
                nt++;
            }
            start += n;
        }
        g_numTiles = nt;
    }
}

__global__ void k_scatter(const int* __restrict__ labels) {
    int i = blockIdx.x * blockDim.x + threadIdx.x;
    if (i < BB) {
        int p = atomicAdd(&g_cursor[labels[i]], 1);
        g_perm[p] = i;
    }
}

// ---------------------------------------------------------------------------
// tf32 helpers
// ---------------------------------------------------------------------------
__device__ __forceinline__ uint32_t f2tf(float x) {
    uint32_t r;
    asm("cvt.rna.tf32.f32 %0, %1;" : "=r"(r) : "f"(x));
    return r;
}

__device__ __forceinline__ void mma8(float* c, const uint32_t* a, const uint32_t* b) {
    asm volatile(
        "mma.sync.aligned.m16n8k8.row.col.f32.tf32.tf32.f32 "
        "{%0,%1,%2,%3}, {%4,%5,%6,%7}, {%8,%9}, {%0,%1,%2,%3};\n"
        : "+f"(c[0]), "+f"(c[1]), "+f"(c[2]), "+f"(c[3])
        : "r"(a[0]), "r"(a[1]), "r"(a[2]), "r"(a[3]), "r"(b[0]), "r"(b[1]));
}

// ---------------------------------------------------------------------------
// GEMM: C[rows x N-tile] = A[rows x K] @ W[K x N] (+bias, epilogue by MODE)
// MODE 0: bias + relu, write Out[grow*N + col]
// MODE 2: dual-weight (mu/lv interleaved in B columns), z-epilogue,
//         write Out[grow*64 + j]   (N passed as 128; logical out width 64)
// MODE 3: bias only, scatter-write Out[perm[grow]*N + col]
// unsharedF: offset W/bias by cluster slab.  permAF: gather A rows via perm.
// Tile: BM=128, BN=128, BK=32. 256 threads, 8 warps in 2(M)x4(N), warp 64x32.
// ---------------------------------------------------------------------------
template <int MODE>
__global__ void __launch_bounds__(256)
k_gemm(const float* __restrict__ A, const float* __restrict__ W,
       const float* __restrict__ W2, const float* __restrict__ bias,
       const float* __restrict__ bias2, float* __restrict__ Out,
       const float* __restrict__ epsp, int K, int N, int unsharedF, int permAF) {
    if ((int)blockIdx.x >= g_numTiles) return;

    __shared__ __align__(16) uint32_t As[128][36];   // padded: conflict-free frags
    __shared__ __align__(16) uint32_t Bs[32][136];

    int4 td = g_tiles[blockIdx.x];
    int rowStart = td.x, rows = td.y, cl = td.z;
    const float* Wp = W + (unsharedF ? (size_t)cl * K * N : 0);
    const float* bp = bias + (unsharedF ? (size_t)cl * N : 0);
    int nb = blockIdx.y * 128;

    int tid = threadIdx.x;
    int warp = tid >> 5, lane = tid & 31;
    int wm = warp >> 2, wn = warp & 3;   // warp tile: rows wm*64, cols wn*32
    int g = lane >> 2, tg = lane & 3;

    float acc[4][4][4];
#pragma unroll
    for (int a = 0; a < 4; a++)
#pragma unroll
        for (int b = 0; b < 4; b++)
#pragma unroll
            for (int d = 0; d < 4; d++) acc[a][b][d] = 0.f;

    for (int kb = 0; kb < K; kb += 32) {
        // ---- stage A tile: 128x32 fp32 -> tf32 smem ----
#pragma unroll
        for (int i = 0; i < 4; i++) {
            int idx = tid + i * 256;
            int r = idx >> 3, kq = (idx & 7) << 2;
            float4 v = make_float4(0.f, 0.f, 0.f, 0.f);
            if (r < rows) {
                int ar = permAF ? g_perm[rowStart + r] : rowStart + r;
                v = *(const float4*)(A + (size_t)ar * K + kb + kq);
            }
            uint4 pv = make_uint4(f2tf(v.x), f2tf(v.y), f2tf(v.z), f2tf(v.w));
            *(uint4*)&As[r][kq] = pv;
        }
        // ---- stage B tile: 32x128 ----
        if (MODE == 2) {
            // interleave: even col n -> mu_W[:, n/2], odd col n -> lv_W[:, n/2]
            for (int idx = tid; idx < 32 * 128; idx += 256) {
                int kr = idx >> 7, n = idx & 127;
                const float* src = (n & 1) ? W2 : W;
                Bs[kr][n] = f2tf(src[(kb + kr) * 64 + (n >> 1)]);
            }
        } else {
#pragma unroll
            for (int i = 0; i < 4; i++) {
                int idx = tid + i * 256;
                int kr = idx >> 5, cq = (idx & 31) << 2;
                float4 v = *(const float4*)(Wp + (size_t)(kb + kr) * N + nb + cq);
                uint4 pv = make_uint4(f2tf(v.x), f2tf(v.y), f2tf(v.z), f2tf(v.w));
                *(uint4*)&Bs[kr][cq] = pv;
            }
        }
        __syncthreads();

        // ---- 4 k-steps of m16n8k8 ----
#pragma unroll
        for (int ks = 0; ks < 4; ks++) {
            uint32_t af[4][4], bf[4][2];
#pragma unroll
            for (int mt = 0; mt < 4; mt++) {
                int r0 = wm * 64 + mt * 16 + g;
                int kk = ks * 8 + tg;
                af[mt][0] = As[r0][kk];
                af[mt][1] = As[r0 + 8][kk];
                af[mt][2] = As[r0][kk + 4];
                af[mt][3] = As[r0 + 8][kk + 4];
            }
#pragma unroll
            for (int nt = 0; nt < 4; nt++) {
                int c0 = wn * 32 + nt * 8 + g;
                bf[nt][0] = Bs[ks * 8 + tg][c0];
                bf[nt][1] = Bs[ks * 8 + tg + 4][c0];
            }
#pragma unroll
            for (int mt = 0; mt < 4; mt++)
#pragma unroll
                for (int nt = 0; nt < 4; nt++)
                    mma8(acc[mt][nt], af[mt], bf[nt]);
        }
        __syncthreads();
    }

    // ---- epilogue ----
#pragma unroll
    for (int mt = 0; mt < 4; mt++) {
#pragma unroll
        for (int nt = 0; nt < 4; nt++) {
            int col = nb + wn * 32 + nt * 8 + 2 * tg;
            float bv0, bv1;
            int j = 0;
            if (MODE == 2) {
                j = wn * 16 + nt * 4 + tg;   // = col/2
                bv0 = bias[j];
                bv1 = bias2[j];
            } else {
                bv0 = bp[col];
                bv1 = bp[col + 1];
            }
#pragma unroll
            for (int h = 0; h < 2; h++) {
                int lr = wm * 64 + mt * 16 + g + h * 8;
                if (lr < rows) {
                    int grow = rowStart + lr;
                    float v0 = acc[mt][nt][2 * h + 0] + bv0;
                    float v1 = acc[mt][nt][2 * h + 1] + bv1;
                    if (MODE == 0) {
                        v0 = fmaxf(v0, 0.f);
                        v1 = fmaxf(v1, 0.f);
                        *(float2*)(Out + (size_t)grow * N + col) = make_float2(v0, v1);
                    } else if (MODE == 2) {
                        int orig = g_perm[grow];
                        float e = epsp[(size_t)orig * 64 + j];
                        Out[(size_t)grow * 64 + j] = v0 + expf(0.5f * v1) * e;
                    } else {  // MODE 3: scatter to original row order, no act
                        int orig = g_perm[grow];
                        *(float2*)(Out + (size_t)orig * N + col) = make_float2(v0, v1);
                    }
                }
            }
        }
    }
}

// ---------------------------------------------------------------------------
// Launch
// ---------------------------------------------------------------------------
extern "C" void kernel_launch(void* const* d_in, const int* in_sizes, int n_in,
                              void* d_out, int out_size) {
    const float* x      = (const float*)d_in[0];
    const int*   lbl    = (const int*)d_in[1];
    const float* eps    = (const float*)d_in[2];
    const float* enc_W0 = (const float*)d_in[3];
    const float* enc_b0 = (const float*)d_in[4];
    const float* enc_Wu = (const float*)d_in[5];
    const float* enc_bu = (const float*)d_in[6];
    const float* enc_W2 = (const float*)d_in[7];
    const float* enc_b2 = (const float*)d_in[8];
    const float* mu_W   = (const float*)d_in[9];
    const float* mu_b   = (const float*)d_in[10];
    const float* lv_W   = (const float*)d_in[11];
    const float* lv_b   = (const float*)d_in[12];
    const float* dWu0   = (const float*)d_in[13];
    const float* dbu0   = (const float*)d_in[14];
    const float* dW1    = (const float*)d_in[15];
    const float* db1    = (const float*)d_in[16];
    const float* dWu2   = (const float*)d_in[17];
    const float* dbu2   = (const float*)d_in[18];
    const float* fW     = (const float*)d_in[19];
    const float* fb     = (const float*)d_in[20];
    float* out = (float*)d_out;

    float *bufA = nullptr, *bufB = nullptr;
    cudaGetSymbolAddress((void**)&bufA, g_bufA);
    cudaGetSymbolAddress((void**)&bufB, g_bufB);

    k_setup<<<1, 256>>>(lbl);
    k_scatter<<<64, 256>>>(lbl);

    // L1: x(perm) @ enc_W0 [512->1024] relu          (shared)
    k_gemm<0><<<dim3(MAXT, 8), 256>>>(x, enc_W0, nullptr, enc_b0, nullptr,
                                      bufA, nullptr, 512, 1024, 0, 1);
    // L2: H1 @ enc_Wu[c] [1024->512] relu            (per-cluster)
    k_gemm<0><<<dim3(MAXT, 4), 256>>>(bufA, enc_Wu, nullptr, enc_bu, nullptr,
                                      bufB, nullptr, 1024, 512, 1, 0);
    // L3: H2 @ enc_W2 [512->256] relu                (shared)
    k_gemm<0><<<dim3(MAXT, 2), 256>>>(bufB, enc_W2, nullptr, enc_b2, nullptr,
                                      bufA, nullptr, 512, 256, 0, 0);
    // L4: mu/lv heads [256->64 each] + reparameterize -> Z
    k_gemm<2><<<dim3(MAXT, 1), 256>>>(bufA, mu_W, lv_W, mu_b, lv_b,
                                      bufB, eps, 256, 128, 0, 0);
    // L5: Z @ dec_Wu0[c] [64->256] relu              (per-cluster)
    k_gemm<0><<<dim3(MAXT, 2), 256>>>(bufB, dWu0, nullptr, dbu0, nullptr,
                                      bufA, nullptr, 64, 256, 1, 0);
    // L6: D1 @ dec_W1 [256->512] relu                (shared)
    k_gemm<0><<<dim3(MAXT, 4), 256>>>(bufA, dW1, nullptr, db1, nullptr,
                                      bufB, nullptr, 256, 512, 0, 0);
    // L7: D2 @ dec_Wu2[c] [512->1024] relu           (per-cluster)
    k_gemm<0><<<dim3(MAXT, 8), 256>>>(bufB, dWu2, nullptr, dbu2, nullptr,
                                      bufA, nullptr, 512, 1024, 1, 0);
    // L8: D3 @ fin_W[c] [1024->512], scatter to original rows (per-cluster)
    k_gemm<3><<<dim3(MAXT, 4), 256>>>(bufA, fW, nullptr, fb, nullptr,
                                      out, nullptr, 1024, 512, 1, 0);
}

// round 2
// speedup vs baseline: 1.1159x; 1.1159x over previous
#include <cuda_runtime.h>
#include <cstdint>

// ============================================================================
// CISSVAE forward on GB300 — R2: cp.async double-buffered tf32 mma pipeline.
// Rows counting-sorted by cluster -> per-cluster layers are dense segment
// GEMMs. Activations are pre-rounded to tf32 in epilogues; x pre-rounded by a
// small pass; B fragments cvt'd at register load. 128x128x32 tiles, 8 warps.
// ============================================================================

#define BB 16384
#define NC 8
#define MAXT 136   // max M tiles: BB/128 + NC

__device__ float g_bufA[BB * 1024];
__device__ float g_bufB[BB * 1024];
__device__ float g_xr[BB * 512];     // tf32-rounded x
__device__ int   g_perm[BB];
__device__ int   g_cursor[NC];
__device__ int4  g_tiles[MAXT];      // {rowStart, rows, cluster, pad}
__device__ int   g_numTiles;

// ---------------------------------------------------------------------------
__global__ void k_setup(const int* __restrict__ labels) {
    __shared__ int cnt[NC];
    int t = threadIdx.x;
    if (t < NC) cnt[t] = 0;
    __syncthreads();
    int loc[NC];
#pragma unroll
    for (int c = 0; c < NC; c++) loc[c] = 0;
    for (int i = t; i < BB; i += blockDim.x) {
        int v = labels[i];
#pragma unroll
        for (int c = 0; c < NC; c++) loc[c] += (v == c);
    }
#pragma unroll
    for (int c = 0; c < NC; c++)
        if (loc[c]) atomicAdd(&cnt[c], loc[c]);
    __syncthreads();
    if (t == 0) {
        int start = 0, nt = 0;
        for (int c = 0; c < NC; c++) {
            g_cursor[c] = start;
            int n = cnt[c];
            for (int off = 0; off < n; off += 128) {
                g_tiles[nt] = make_int4(start + off, min(128, n - off), c, 0);
                nt++;
            }
            start += n;
        }
        g_numTiles = nt;
    }
}

__global__ void k_scatter(const int* __restrict__ labels) {
    int i = blockIdx.x * blockDim.x + threadIdx.x;
    if (i < BB) {
        int p = atomicAdd(&g_cursor[labels[i]], 1);
        g_perm[p] = i;
    }
}

// ---------------------------------------------------------------------------
__device__ __forceinline__ uint32_t f2tf(float x) {
    uint32_t r;
    asm("cvt.rna.tf32.f32 %0, %1;" : "=r"(r) : "f"(x));
    return r;
}
__device__ __forceinline__ float roundtf(float x) {
    return __uint_as_float(f2tf(x));
}

__global__ void k_round(const float* __restrict__ in, float* __restrict__ out, int n4) {
    int i = blockIdx.x * blockDim.x + threadIdx.x;
    if (i < n4) {
        float4 v = ((const float4*)in)[i];
        v.x = roundtf(v.x); v.y = roundtf(v.y);
        v.z = roundtf(v.z); v.w = roundtf(v.w);
        ((float4*)out)[i] = v;
    }
}

__device__ __forceinline__ void mma8(float* c, const uint32_t* a, const uint32_t* b) {
    asm volatile(
        "mma.sync.aligned.m16n8k8.row.col.f32.tf32.tf32.f32 "
        "{%0,%1,%2,%3}, {%4,%5,%6,%7}, {%8,%9}, {%0,%1,%2,%3};\n"
        : "+f"(c[0]), "+f"(c[1]), "+f"(c[2]), "+f"(c[3])
        : "r"(a[0]), "r"(a[1]), "r"(a[2]), "r"(a[3]), "r"(b[0]), "r"(b[1]));
}

__device__ __forceinline__ void cp16(void* s, const void* g, int szbytes) {
    uint32_t sa = (uint32_t)__cvta_generic_to_shared(s);
    asm volatile("cp.async.cg.shared.global [%0], [%1], 16, %2;\n"
                 :: "r"(sa), "l"(g), "r"(szbytes));
}
#define CP_COMMIT() asm volatile("cp.async.commit_group;\n")
#define CP_WAIT1()  asm volatile("cp.async.wait_group 1;\n")

// ---------------------------------------------------------------------------
// Pipelined GEMM. MODE 0: bias+relu+tf32-round. MODE 3: bias, scatter, no act.
// Smem layout (floats): As[2][128][36] then Bs[2][32][136].
// ---------------------------------------------------------------------------
#define AST 4608   // 128*36
#define BST 4352   // 32*136
#define BOFF 9216  // 2*AST
#define SMEM_BYTES ((BOFF + 2 * BST) * 4)

template <int MODE>
__global__ void __launch_bounds__(256, 2)
k_gemm(const float* __restrict__ A, const float* __restrict__ W,
       const float* __restrict__ bias, float* __restrict__ Out,
       int K, int N, int unsharedF, int permAF) {
    if ((int)blockIdx.x >= g_numTiles) return;
    extern __shared__ float sm[];

    int4 td = g_tiles[blockIdx.x];
    int rowStart = td.x, rows = td.y, cl = td.z;
    const float* Wp = W + (unsharedF ? (size_t)cl * K * N : 0);
    const float* bp = bias + (unsharedF ? (size_t)cl * N : 0);
    int nb = blockIdx.y * 128;

    int tid = threadIdx.x;
    int warp = tid >> 5, lane = tid & 31;
    int wm = warp >> 2, wn = warp & 3;
    int g = lane >> 2, tg = lane & 3;

    float acc[4][4][4];
#pragma unroll
    for (int a = 0; a < 4; a++)
#pragma unroll
        for (int b = 0; b < 4; b++)
#pragma unroll
            for (int d = 0; d < 4; d++) acc[a][b][d] = 0.f;

    // per-thread load coordinates (4 A chunks + 4 B chunks of 16B each)
    auto loadTile = [&](int kb, int s) {
        float* Asf = sm + s * AST;
        float* Bsf = sm + BOFF + s * BST;
#pragma unroll
        for (int i = 0; i < 4; i++) {
            int idx = tid + i * 256;
            int r = idx >> 3, kq = (idx & 7) << 2;
            int ok = (r < rows);
            int ar = ok ? (permAF ? g_perm[rowStart + r] : rowStart + r) : 0;
            cp16(Asf + r * 36 + kq, A + (size_t)ar * K + kb + kq, ok ? 16 : 0);
        }
#pragma unroll
        for (int i = 0; i < 4; i++) {
            int idx = tid + i * 256;
            int kr = idx >> 5, cq = (idx & 31) << 2;
            cp16(Bsf + kr * 136 + cq, Wp + (size_t)(kb + kr) * N + nb + cq, 16);
        }
    };

    int nk = K >> 5;
    int buf = 0;
    loadTile(0, 0);
    CP_COMMIT();

    for (int i = 0; i < nk; i++) {
        if (i + 1 < nk) loadTile((i + 1) << 5, buf ^ 1);
        CP_COMMIT();
        CP_WAIT1();
        __syncthreads();

        const float* Asf = sm + buf * AST;
        const float* Bsf = sm + BOFF + buf * BST;
#pragma unroll
        for (int ks = 0; ks < 4; ks++) {
            uint32_t af[4][4], bf[4][2];
#pragma unroll
            for (int mt = 0; mt < 4; mt++) {
                int r0 = wm * 64 + mt * 16 + g;
                int kk = ks * 8 + tg;
                af[mt][0] = __float_as_uint(Asf[r0 * 36 + kk]);
                af[mt][1] = __float_as_uint(Asf[(r0 + 8) * 36 + kk]);
                af[mt][2] = __float_as_uint(Asf[r0 * 36 + kk + 4]);
                af[mt][3] = __float_as_uint(Asf[(r0 + 8) * 36 + kk + 4]);
            }
#pragma unroll
            for (int nt = 0; nt < 4; nt++) {
                int c0 = wn * 32 + nt * 8 + g;
                bf[nt][0] = f2tf(Bsf[(ks * 8 + tg) * 136 + c0]);
                bf[nt][1] = f2tf(Bsf[(ks * 8 + tg + 4) * 136 + c0]);
            }
#pragma unroll
            for (int mt = 0; mt < 4; mt++)
#pragma unroll
                for (int nt = 0; nt < 4; nt++)
                    mma8(acc[mt][nt], af[mt], bf[nt]);
        }
        buf ^= 1;
        __syncthreads();
    }

    // ---- epilogue ----
#pragma unroll
    for (int mt = 0; mt < 4; mt++) {
#pragma unroll
        for (int nt = 0; nt < 4; nt++) {
            int col = nb + wn * 32 + nt * 8 + 2 * tg;
            float bv0 = bp[col], bv1 = bp[col + 1];
#pragma unroll
            for (int h = 0; h < 2; h++) {
                int lr = wm * 64 + mt * 16 + g + h * 8;
                if (lr < rows) {
                    int grow = rowStart + lr;
                    float v0 = acc[mt][nt][2 * h + 0] + bv0;
                    float v1 = acc[mt][nt][2 * h + 1] + bv1;
                    if (MODE == 0) {
                        v0 = roundtf(fmaxf(v0, 0.f));
                        v1 = roundtf(fmaxf(v1, 0.f));
                        *(float2*)(Out + (size_t)grow * N + col) = make_float2(v0, v1);
                    } else {  // MODE 3: scatter to original row order, no act
                        int orig = g_perm[grow];
                        *(float2*)(Out + (size_t)orig * N + col) = make_float2(v0, v1);
                    }
                }
            }
        }
    }
}

// ---------------------------------------------------------------------------
// mu/lv dual-head + reparameterization (small layer, sync staging kept).
// B cols interleaved: even -> mu_W[:,c/2], odd -> lv_W[:,c/2]. K=256, Nlog=64.
// ---------------------------------------------------------------------------
__global__ void __launch_bounds__(256)
k_gemm_z(const float* __restrict__ A, const float* __restrict__ W,
         const float* __restrict__ W2, const float* __restrict__ bias,
         const float* __restrict__ bias2, float* __restrict__ Out,
         const float* __restrict__ epsp, int K) {
    if ((int)blockIdx.x >= g_numTiles) return;
    __shared__ __align__(16) uint32_t As[128][36];
    __shared__ __align__(16) uint32_t Bs[32][136];

    int4 td = g_tiles[blockIdx.x];
    int rowStart = td.x, rows = td.y;

    int tid = threadIdx.x;
    int warp = tid >> 5, lane = tid & 31;
    int wm = warp >> 2, wn = warp & 3;
    int g = lane >> 2, tg = lane & 3;

    float acc[4][4][4];
#pragma unroll
    for (int a = 0; a < 4; a++)
#pragma unroll
        for (int b = 0; b < 4; b++)
#pragma unroll
            for (int d = 0; d < 4; d++) acc[a][b][d] = 0.f;

    for (int kb = 0; kb < K; kb += 32) {
#pragma unroll
        for (int i = 0; i < 4; i++) {
            int idx = tid + i * 256;
            int r = idx >> 3, kq = (idx & 7) << 2;
            float4 v = make_float4(0.f, 0.f, 0.f, 0.f);
            if (r < rows)
                v = *(const float4*)(A + (size_t)(rowStart + r) * K + kb + kq);
            *(uint4*)&As[r][kq] = make_uint4(f2tf(v.x), f2tf(v.y), f2tf(v.z), f2tf(v.w));
        }
        for (int idx = tid; idx < 32 * 128; idx += 256) {
            int kr = idx >> 7, n = idx & 127;
            const float* src = (n & 1) ? W2 : W;
            Bs[kr][n] = f2tf(src[(kb + kr) * 64 + (n >> 1)]);
        }
        __syncthreads();
#pragma unroll
        for (int ks = 0; ks < 4; ks++) {
            uint32_t af[4][4], bf[4][2];
#pragma unroll
            for (int mt = 0; mt < 4; mt++) {
                int r0 = wm * 64 + mt * 16 + g;
                int kk = ks * 8 + tg;
                af[mt][0] = As[r0][kk];
                af[mt][1] = As[r0 + 8][kk];
                af[mt][2] = As[r0][kk + 4];
                af[mt][3] = As[r0 + 8][kk + 4];
            }
#pragma unroll
            for (int nt = 0; nt < 4; nt++) {
                int c0 = wn * 32 + nt * 8 + g;
                bf[nt][0] = Bs[ks * 8 + tg][c0];
                bf[nt][1] = Bs[ks * 8 + tg + 4][c0];
            }
#pragma unroll
            for (int mt = 0; mt < 4; mt++)
#pragma unroll
                for (int nt = 0; nt < 4; nt++)
                    mma8(acc[mt][nt], af[mt], bf[nt]);
        }
        __syncthreads();
    }

#pragma unroll
    for (int mt = 0; mt < 4; mt++) {
#pragma unroll
        for (int nt = 0; nt < 4; nt++) {
            int j = wn * 16 + nt * 4 + tg;   // latent index
            float bmu = bias[j], blv = bias2[j];
#pragma unroll
            for (int h = 0; h < 2; h++) {
                int lr = wm * 64 + mt * 16 + g + h * 8;
                if (lr < rows) {
                    int grow = rowStart + lr;
                    int orig = g_perm[grow];
                    float mu = acc[mt][nt][2 * h + 0] + bmu;
                    float lv = acc[mt][nt][2 * h + 1] + blv;
                    float e = epsp[(size_t)orig * 64 + j];
                    Out[(size_t)grow * 64 + j] = roundtf(mu + expf(0.5f * lv) * e);
                }
            }
        }
    }
}

// ---------------------------------------------------------------------------
extern "C" void kernel_launch(void* const* d_in, const int* in_sizes, int n_in,
                              void* d_out, int out_size) {
    const float* x      = (const float*)d_in[0];
    const int*   lbl    = (const int*)d_in[1];
    const float* eps    = (const float*)d_in[2];
    const float* enc_W0 = (const float*)d_in[3];
    const float* enc_b0 = (const float*)d_in[4];
    const float* enc_Wu = (const float*)d_in[5];
    const float* enc_bu = (const float*)d_in[6];
    const float* enc_W2 = (const float*)d_in[7];
    const float* enc_b2 = (const float*)d_in[8];
    const float* mu_W   = (const float*)d_in[9];
    const float* mu_b   = (const float*)d_in[10];
    const float* lv_W   = (const float*)d_in[11];
    const float* lv_b   = (const float*)d_in[12];
    const float* dWu0   = (const float*)d_in[13];
    const float* dbu0   = (const float*)d_in[14];
    const float* dW1    = (const float*)d_in[15];
    const float* db1    = (const float*)d_in[16];
    const float* dWu2   = (const float*)d_in[17];
    const float* dbu2   = (const float*)d_in[18];
    const float* fW     = (const float*)d_in[19];
    const float* fb     = (const float*)d_in[20];
    float* out = (float*)d_out;

    float *bufA = nullptr, *bufB = nullptr, *xr = nullptr;
    cudaGetSymbolAddress((void**)&bufA, g_bufA);
    cudaGetSymbolAddress((void**)&bufB, g_bufB);
    cudaGetSymbolAddress((void**)&xr,   g_xr);

    static int attrDone = 0;
    if (!attrDone) {
        cudaFuncSetAttribute(k_gemm<0>, cudaFuncAttributeMaxDynamicSharedMemorySize, SMEM_BYTES);
        cudaFuncSetAttribute(k_gemm<3>, cudaFuncAttributeMaxDynamicSharedMemorySize, SMEM_BYTES);
        attrDone = 1;
    }

    k_setup<<<1, 256>>>(lbl);
    k_scatter<<<64, 256>>>(lbl);
    k_round<<<(BB * 512 / 4 + 255) / 256, 256>>>(x, xr, BB * 512 / 4);

    // L1: xr(perm) @ enc_W0 [512->1024] relu          (shared)
    k_gemm<0><<<dim3(MAXT, 8), 256, SMEM_BYTES>>>(xr, enc_W0, enc_b0, bufA, 512, 1024, 0, 1);
    // L2: H1 @ enc_Wu[c] [1024->512] relu             (per-cluster)
    k_gemm<0><<<dim3(MAXT, 4), 256, SMEM_BYTES>>>(bufA, enc_Wu, enc_bu, bufB, 1024, 512, 1, 0);
    // L3: H2 @ enc_W2 [512->256] relu                 (shared)
    k_gemm<0><<<dim3(MAXT, 2), 256, SMEM_BYTES>>>(bufB, enc_W2, enc_b2, bufA, 512, 256, 0, 0);
    // L4: mu/lv heads [256->64 each] + reparameterize -> Z
    k_gemm_z<<<dim3(MAXT, 1), 256>>>(bufA, mu_W, lv_W, mu_b, lv_b, bufB, eps, 256);
    // L5: Z @ dec_Wu0[c] [64->256] relu               (per-cluster)
    k_gemm<0><<<dim3(MAXT, 2), 256, SMEM_BYTES>>>(bufB, dWu0, dbu0, bufA, 64, 256, 1, 0);
    // L6: D1 @ dec_W1 [256->512] relu                 (shared)
    k_gemm<0><<<dim3(MAXT, 4), 256, SMEM_BYTES>>>(bufA, dW1, db1, bufB, 256, 512, 0, 0);
    // L7: D2 @ dec_Wu2[c] [512->1024] relu            (per-cluster)
    k_gemm<0><<<dim3(MAXT, 8), 256, SMEM_BYTES>>>(bufB, dWu2, dbu2, bufA, 512, 1024, 1, 0);
    // L8: D3 @ fin_W[c] [1024->512], scatter to orig rows (per-cluster)
    k_gemm<3><<<dim3(MAXT, 4), 256, SMEM_BYTES>>>(bufA, fW, fb, out, 1024, 512, 1, 0);
}

// round 3
// speedup vs baseline: 1.1699x; 1.0485x over previous
#include <cuda_runtime.h>
#include <cstdint>

// ============================================================================
// CISSVAE forward on GB300 — R3: issue-slimmed tf32 pipeline.
// ldmatrix.x4 A fragments, pre-rounded weights (no cvt in mainloop),
// compile-time K/N, cp.async double buffering. Rows counting-sorted by
// cluster so per-cluster layers are dense segment GEMMs.
// ============================================================================

#define BB 16384
#define NC 8
#define MAXT 136

__device__ float g_bufA[BB * 1024];
__device__ float g_bufB[BB * 1024];
__device__ float g_xr[BB * 512];
__device__ float g_wr[13500416];     // pre-rounded weights
__device__ int   g_perm[BB];
__device__ int   g_cursor[NC];
__device__ int4  g_tiles[MAXT];
__device__ int   g_numTiles;

// weight offsets inside g_wr
#define O_EW0   0
#define O_EWU   524288
#define O_EW2   4718592
#define O_DWU0  4849664
#define O_DW1   4980736
#define O_DWU2  5111808
#define O_FW    9306112

// ---------------------------------------------------------------------------
__global__ void k_setup(const int* __restrict__ labels) {
    __shared__ int cnt[NC];
    int t = threadIdx.x;
    if (t < NC) cnt[t] = 0;
    __syncthreads();
    int loc[NC];
#pragma unroll
    for (int c = 0; c < NC; c++) loc[c] = 0;
    for (int i = t; i < BB; i += blockDim.x) {
        int v = labels[i];
#pragma unroll
        for (int c = 0; c < NC; c++) loc[c] += (v == c);
    }
#pragma unroll
    for (int c = 0; c < NC; c++)
        if (loc[c]) atomicAdd(&cnt[c], loc[c]);
    __syncthreads();
    if (t == 0) {
        int start = 0, nt = 0;
        for (int c = 0; c < NC; c++) {
            g_cursor[c] = start;
            int n = cnt[c];
            for (int off = 0; off < n; off += 128) {
                g_tiles[nt] = make_int4(start + off, min(128, n - off), c, 0);
                nt++;
            }
            start += n;
        }
        g_numTiles = nt;
    }
}

__global__ void k_scatter(const int* __restrict__ labels) {
    int i = blockIdx.x * blockDim.x + threadIdx.x;
    if (i < BB) {
        int p = atomicAdd(&g_cursor[labels[i]], 1);
        g_perm[p] = i;
    }
}

// ---------------------------------------------------------------------------
__device__ __forceinline__ uint32_t f2tf(float x) {
    uint32_t r;
    asm("cvt.rna.tf32.f32 %0, %1;" : "=r"(r) : "f"(x));
    return r;
}
__device__ __forceinline__ float roundtf(float x) {
    return __uint_as_float(f2tf(x));
}

__global__ void k_round(const float* __restrict__ in, float* __restrict__ out, int n4) {
    int i = blockIdx.x * blockDim.x + threadIdx.x;
    if (i < n4) {
        float4 v = ((const float4*)in)[i];
        v.x = roundtf(v.x); v.y = roundtf(v.y);
        v.z = roundtf(v.z); v.w = roundtf(v.w);
        ((float4*)out)[i] = v;
    }
}

__device__ __forceinline__ void mma8(float* c, const uint32_t* a, const uint32_t* b) {
    asm volatile(
        "mma.sync.aligned.m16n8k8.row.col.f32.tf32.tf32.f32 "
        "{%0,%1,%2,%3}, {%4,%5,%6,%7}, {%8,%9}, {%0,%1,%2,%3};\n"
        : "+f"(c[0]), "+f"(c[1]), "+f"(c[2]), "+f"(c[3])
        : "r"(a[0]), "r"(a[1]), "r"(a[2]), "r"(a[3]), "r"(b[0]), "r"(b[1]));
}

__device__ __forceinline__ void ldsm4(uint32_t* r, uint32_t saddr) {
    asm volatile("ldmatrix.sync.aligned.m8n8.x4.shared.b16 {%0,%1,%2,%3}, [%4];"
                 : "=r"(r[0]), "=r"(r[1]), "=r"(r[2]), "=r"(r[3]) : "r"(saddr));
}

__device__ __forceinline__ void cp16(uint32_t saddr, const void* g, int szbytes) {
    asm volatile("cp.async.cg.shared.global [%0], [%1], 16, %2;\n"
                 :: "r"(saddr), "l"(g), "r"(szbytes));
}
#define CP_COMMIT() asm volatile("cp.async.commit_group;\n")
#define CP_WAIT1()  asm volatile("cp.async.wait_group 1;\n")

// ---------------------------------------------------------------------------
#define AST 4608   // 128*36 floats
#define BST 4352   // 32*136 floats
#define BOFF 9216
#define SMEM_BYTES ((BOFF + 2 * BST) * 4)

template <int MODE, int K, int N>
__global__ void __launch_bounds__(256, 2)
k_gemm(const float* __restrict__ A, const float* __restrict__ W,
       const float* __restrict__ bias, float* __restrict__ Out,
       int unsharedF, int permAF) {
    if ((int)blockIdx.x >= g_numTiles) return;
    extern __shared__ float sm[];

    int4 td = g_tiles[blockIdx.x];
    int rowStart = td.x, rows = td.y, cl = td.z;
    const float* Wp = W + (unsharedF ? (size_t)cl * K * N : 0);
    const float* bp = bias + (unsharedF ? (size_t)cl * N : 0);
    int nb = blockIdx.y * 128;

    int tid = threadIdx.x;
    int warp = tid >> 5, lane = tid & 31;
    int wm = warp >> 2, wn = warp & 3;
    int g = lane >> 2, tg = lane & 3;

    uint32_t smBase = (uint32_t)__cvta_generic_to_shared(sm);

    // ---- per-thread staging coordinates (hoisted) ----
    const float* aP[4]; int aSz[4]; uint32_t sA[4];
    const float* bP[4]; uint32_t sB[4];
#pragma unroll
    for (int i = 0; i < 4; i++) {
        int idx = tid + i * 256;
        int r = idx >> 3, kq = (idx & 7) << 2;
        int ok = (r < rows);
        aSz[i] = ok ? 16 : 0;
        int ar = ok ? (permAF ? g_perm[rowStart + r] : rowStart + r) : 0;
        aP[i] = A + (size_t)ar * K + kq;
        sA[i] = smBase + 4u * (r * 36 + kq);
        int kr = idx >> 5, cq = (idx & 31) << 2;
        bP[i] = Wp + (size_t)kr * N + nb + cq;
        sB[i] = smBase + 4u * (BOFF + kr * 136 + cq);
    }

    // ---- ldmatrix lane address base ----
    int m4 = lane >> 3, rw = lane & 7;
    uint32_t aFrag = smBase + 4u * ((wm * 64 + (m4 & 1) * 8 + rw) * 36 + ((m4 >> 1) << 2));

    float acc[4][4][4];
#pragma unroll
    for (int a = 0; a < 4; a++)
#pragma unroll
        for (int b = 0; b < 4; b++)
#pragma unroll
            for (int d = 0; d < 4; d++) acc[a][b][d] = 0.f;

    auto loadTile = [&](int s) {
#pragma unroll
        for (int i = 0; i < 4; i++) {
            cp16(sA[i] + (uint32_t)s * (AST * 4), aP[i], aSz[i]);
            aP[i] += 32;
        }
#pragma unroll
        for (int i = 0; i < 4; i++) {
            cp16(sB[i] + (uint32_t)s * (BST * 4), bP[i], 16);
            bP[i] += 32 * N;
        }
    };

    const int nk = K >> 5;
    int buf = 0;
    loadTile(0);
    CP_COMMIT();

    for (int i = 0; i < nk; i++) {
        if (i + 1 < nk) loadTile(buf ^ 1);
        CP_COMMIT();
        CP_WAIT1();
        __syncthreads();

        const float* Bsf = sm + BOFF + buf * BST;
        uint32_t aBuf = aFrag + (uint32_t)buf * (AST * 4);
        int c0base = wn * 32 + g;
#pragma unroll
        for (int ks = 0; ks < 4; ks++) {
            uint32_t af[4][4], bf[4][2];
#pragma unroll
            for (int mt = 0; mt < 4; mt++)
                ldsm4(af[mt], aBuf + 4u * (mt * 576 + ks * 8));
#pragma unroll
            for (int nt = 0; nt < 4; nt++) {
                int c0 = c0base + nt * 8;
                bf[nt][0] = __float_as_uint(Bsf[(ks * 8 + tg) * 136 + c0]);
                bf[nt][1] = __float_as_uint(Bsf[(ks * 8 + tg + 4) * 136 + c0]);
            }
#pragma unroll
            for (int mt = 0; mt < 4; mt++)
#pragma unroll
                for (int nt = 0; nt < 4; nt++)
                    mma8(acc[mt][nt], af[mt], bf[nt]);
        }
        buf ^= 1;
        __syncthreads();
    }

    // ---- epilogue ----
#pragma unroll
    for (int mt = 0; mt < 4; mt++) {
#pragma unroll
        for (int nt = 0; nt < 4; nt++) {
            int col = nb + wn * 32 + nt * 8 + 2 * tg;
            float bv0 = bp[col], bv1 = bp[col + 1];
#pragma unroll
            for (int h = 0; h < 2; h++) {
                int lr = wm * 64 + mt * 16 + g + h * 8;
                if (lr < rows) {
                    int grow = rowStart + lr;
                    float v0 = acc[mt][nt][2 * h + 0] + bv0;
                    float v1 = acc[mt][nt][2 * h + 1] + bv1;
                    if (MODE == 0) {
                        v0 = roundtf(fmaxf(v0, 0.f));
                        v1 = roundtf(fmaxf(v1, 0.f));
                        *(float2*)(Out + (size_t)grow * N + col) = make_float2(v0, v1);
                    } else {  // MODE 3: scatter to original rows, no activation
                        int orig = g_perm[grow];
                        *(float2*)(Out + (size_t)orig * N + col) = make_float2(v0, v1);
                    }
                }
            }
        }
    }
}

// ---------------------------------------------------------------------------
// mu/lv dual-head + reparameterization (small; sync staging, cvt at stage).
// ---------------------------------------------------------------------------
__global__ void __launch_bounds__(256)
k_gemm_z(const float* __restrict__ A, const float* __restrict__ W,
         const float* __restrict__ W2, const float* __restrict__ bias,
         const float* __restrict__ bias2, float* __restrict__ Out,
         const float* __restrict__ epsp, int K) {
    if ((int)blockIdx.x >= g_numTiles) return;
    __shared__ __align__(16) uint32_t As[128][36];
    __shared__ __align__(16) uint32_t Bs[32][136];

    int4 td = g_tiles[blockIdx.x];
    int rowStart = td.x, rows = td.y;

    int tid = threadIdx.x;
    int warp = tid >> 5, lane = tid & 31;
    int wm = warp >> 2, wn = warp & 3;
    int g = lane >> 2, tg = lane & 3;

    float acc[4][4][4];
#pragma unroll
    for (int a = 0; a < 4; a++)
#pragma unroll
        for (int b = 0; b < 4; b++)
#pragma unroll
            for (int d = 0; d < 4; d++) acc[a][b][d] = 0.f;

    for (int kb = 0; kb < K; kb += 32) {
#pragma unroll
        for (int i = 0; i < 4; i++) {
            int idx = tid + i * 256;
            int r = idx >> 3, kq = (idx & 7) << 2;
            float4 v = make_float4(0.f, 0.f, 0.f, 0.f);
            if (r < rows)
                v = *(const float4*)(A + (size_t)(rowStart + r) * K + kb + kq);
            *(uint4*)&As[r][kq] = make_uint4(f2tf(v.x), f2tf(v.y), f2tf(v.z), f2tf(v.w));
        }
        for (int idx = tid; idx < 32 * 128; idx += 256) {
            int kr = idx >> 7, n = idx & 127;
            const float* src = (n & 1) ? W2 : W;
            Bs[kr][n] = f2tf(src[(kb + kr) * 64 + (n >> 1)]);
        }
        __syncthreads();
#pragma unroll
        for (int ks = 0; ks < 4; ks++) {
            uint32_t af[4][4], bf[4][2];
#pragma unroll
            for (int mt = 0; mt < 4; mt++) {
                int r0 = wm * 64 + mt * 16 + g;
                int kk = ks * 8 + tg;
                af[mt][0] = As[r0][kk];
                af[mt][1] = As[r0 + 8][kk];
                af[mt][2] = As[r0][kk + 4];
                af[mt][3] = As[r0 + 8][kk + 4];
            }
#pragma unroll
            for (int nt = 0; nt < 4; nt++) {
                int c0 = wn * 32 + nt * 8 + g;
                bf[nt][0] = Bs[ks * 8 + tg][c0];
                bf[nt][1] = Bs[ks * 8 + tg + 4][c0];
            }
#pragma unroll
            for (int mt = 0; mt < 4; mt++)
#pragma unroll
                for (int nt = 0; nt < 4; nt++)
                    mma8(acc[mt][nt], af[mt], bf[nt]);
        }
        __syncthreads();
    }

#pragma unroll
    for (int mt = 0; mt < 4; mt++) {
#pragma unroll
        for (int nt = 0; nt < 4; nt++) {
            int j = wn * 16 + nt * 4 + tg;
            float bmu = bias[j], blv = bias2[j];
#pragma unroll
            for (int h = 0; h < 2; h++) {
                int lr = wm * 64 + mt * 16 + g + h * 8;
                if (lr < rows) {
                    int grow = rowStart + lr;
                    int orig = g_perm[grow];
                    float mu = acc[mt][nt][2 * h + 0] + bmu;
                    float lv = acc[mt][nt][2 * h + 1] + blv;
                    float e = epsp[(size_t)orig * 64 + j];
                    Out[(size_t)grow * 64 + j] = roundtf(mu + expf(0.5f * lv) * e);
                }
            }
        }
    }
}

// ---------------------------------------------------------------------------
extern "C" void kernel_launch(void* const* d_in, const int* in_sizes, int n_in,
                              void* d_out, int out_size) {
    const float* x      = (const float*)d_in[0];
    const int*   lbl    = (const int*)d_in[1];
    const float* eps    = (const float*)d_in[2];
    const float* enc_W0 = (const float*)d_in[3];
    const float* enc_b0 = (const float*)d_in[4];
    const float* enc_Wu = (const float*)d_in[5];
    const float* enc_bu = (const float*)d_in[6];
    const float* enc_W2 = (const float*)d_in[7];
    const float* enc_b2 = (const float*)d_in[8];
    const float* mu_W   = (const float*)d_in[9];
    const float* mu_b   = (const float*)d_in[10];
    const float* lv_W   = (const float*)d_in[11];
    const float* lv_b   = (const float*)d_in[12];
    const float* dWu0   = (const float*)d_in[13];
    const float* dbu0   = (const float*)d_in[14];
    const float* dW1    = (const float*)d_in[15];
    const float* db1    = (const float*)d_in[16];
    const float* dWu2   = (const float*)d_in[17];
    const float* dbu2   = (const float*)d_in[18];
    const float* fW     = (const float*)d_in[19];
    const float* fb     = (const float*)d_in[20];
    float* out = (float*)d_out;

    float *bufA, *bufB, *xr, *wr;
    cudaGetSymbolAddress((void**)&bufA, g_bufA);
    cudaGetSymbolAddress((void**)&bufB, g_bufB);
    cudaGetSymbolAddress((void**)&xr,   g_xr);
    cudaGetSymbolAddress((void**)&wr,   g_wr);

    static int attrDone = 0;
    if (!attrDone) {
        cudaFuncSetAttribute(k_gemm<0, 512, 1024>, cudaFuncAttributeMaxDynamicSharedMemorySize, SMEM_BYTES);
        cudaFuncSetAttribute(k_gemm<0, 1024, 512>, cudaFuncAttributeMaxDynamicSharedMemorySize, SMEM_BYTES);
        cudaFuncSetAttribute(k_gemm<0, 512, 256>,  cudaFuncAttributeMaxDynamicSharedMemorySize, SMEM_BYTES);
        cudaFuncSetAttribute(k_gemm<0, 64, 256>,   cudaFuncAttributeMaxDynamicSharedMemorySize, SMEM_BYTES);
        cudaFuncSetAttribute(k_gemm<0, 256, 512>,  cudaFuncAttributeMaxDynamicSharedMemorySize, SMEM_BYTES);
        cudaFuncSetAttribute(k_gemm<3, 1024, 512>, cudaFuncAttributeMaxDynamicSharedMemorySize, SMEM_BYTES);
        attrDone = 1;
    }

    k_setup<<<1, 256>>>(lbl);
    k_scatter<<<64, 256>>>(lbl);

    // pre-round x and weights to tf32
    k_round<<<(BB * 512 / 4 + 255) / 256, 256>>>(x, xr, BB * 512 / 4);
    k_round<<<(524288 / 4 + 255) / 256, 256>>>(enc_W0, wr + O_EW0, 524288 / 4);
    k_round<<<(4194304 / 4 + 255) / 256, 256>>>(enc_Wu, wr + O_EWU, 4194304 / 4);
    k_round<<<(131072 / 4 + 255) / 256, 256>>>(enc_W2, wr + O_EW2, 131072 / 4);
    k_round<<<(131072 / 4 + 255) / 256, 256>>>(dWu0, wr + O_DWU0, 131072 / 4);
    k_round<<<(131072 / 4 + 255) / 256, 256>>>(dW1, wr + O_DW1, 131072 / 4);
    k_round<<<(4194304 / 4 + 255) / 256, 256>>>(dWu2, wr + O_DWU2, 4194304 / 4);
    k_round<<<(4194304 / 4 + 255) / 256, 256>>>(fW, wr + O_FW, 4194304 / 4);

    // L1: xr(perm) @ enc_W0 [512->1024] relu
    k_gemm<0, 512, 1024><<<dim3(MAXT, 8), 256, SMEM_BYTES>>>(xr, wr + O_EW0, enc_b0, bufA, 0, 1);
    // L2: H1 @ enc_Wu[c] [1024->512] relu
    k_gemm<0, 1024, 512><<<dim3(MAXT, 4), 256, SMEM_BYTES>>>(bufA, wr + O_EWU, enc_bu, bufB, 1, 0);
    // L3: H2 @ enc_W2 [512->256] relu
    k_gemm<0, 512, 256><<<dim3(MAXT, 2), 256, SMEM_BYTES>>>(bufB, wr + O_EW2, enc_b2, bufA, 0, 0);
    // L4: mu/lv heads + reparameterize -> Z
    k_gemm_z<<<dim3(MAXT, 1), 256>>>(bufA, mu_W, lv_W, mu_b, lv_b, bufB, eps, 256);
    // L5: Z @ dec_Wu0[c] [64->256] relu
    k_gemm<0, 64, 256><<<dim3(MAXT, 2), 256, SMEM_BYTES>>>(bufB, wr + O_DWU0, dbu0, bufA, 1, 0);
    // L6: D1 @ dec_W1 [256->512] relu
    k_gemm<0, 256, 512><<<dim3(MAXT, 4), 256, SMEM_BYTES>>>(bufA, wr + O_DW1, db1, bufB, 0, 0);
    // L7: D2 @ dec_Wu2[c] [512->1024] relu
    k_gemm<0, 512, 1024><<<dim3(MAXT, 8), 256, SMEM_BYTES>>>(bufB, wr + O_DWU2, dbu2, bufA, 1, 0);
    // L8: D3 @ fin_W[c] [1024->512], scatter to original rows
    k_gemm<3, 1024, 512><<<dim3(MAXT, 4), 256, SMEM_BYTES>>>(bufA, wr + O_FW, fb, out, 1, 0);
}

// round 5
// speedup vs baseline: 1.7711x; 1.5139x over previous
#include <cuda_runtime.h>
#include <cuda_fp16.h>
#include <cstdint>

// ============================================================================
// CISSVAE forward on GB300 — R5: fp16 mma.sync m16n8k16 (fp32 accum).
// Rows counting-sorted by cluster -> per-cluster layers are dense segment
// GEMMs. Weights/x/activations stored fp16; ldmatrix fragments; cp.async
// double-buffered 128x128x32 tiles; fused bias/ReLU/reparam epilogues.
// ============================================================================

#define BB 16384
#define NC 8
#define MAXT 136

__device__ __half g_bufA[BB * 1024];
__device__ __half g_bufB[BB * 1024];
__device__ __half g_xh[BB * 512];
__device__ __half g_wh[13500416];   // fp16 weights, original [K][N] layout
__device__ int    g_perm[BB];
__device__ int    g_cursor[NC];
__device__ int4   g_tiles[MAXT];
__device__ int    g_numTiles;

#define O_EW0   0
#define O_EWU   524288
#define O_EW2   4718592
#define O_DWU0  4849664
#define O_DW1   4980736
#define O_DWU2  5111808
#define O_FW    9306112

// ---------------------------------------------------------------------------
__global__ void k_setup(const int* __restrict__ labels) {
    __shared__ int cnt[NC];
    int t = threadIdx.x;
    if (t < NC) cnt[t] = 0;
    __syncthreads();
    int loc[NC];
#pragma unroll
    for (int c = 0; c < NC; c++) loc[c] = 0;
    for (int i = t; i < BB; i += blockDim.x) {
        int v = labels[i];
#pragma unroll
        for (int c = 0; c < NC; c++) loc[c] += (v == c);
    }
#pragma unroll
    for (int c = 0; c < NC; c++)
        if (loc[c]) atomicAdd(&cnt[c], loc[c]);
    __syncthreads();
    if (t == 0) {
        int start = 0, nt = 0;
        for (int c = 0; c < NC; c++) {
            g_cursor[c] = start;
            int n = cnt[c];
            for (int off = 0; off < n; off += 128) {
                g_tiles[nt] = make_int4(start + off, min(128, n - off), c, 0);
                nt++;
            }
            start += n;
        }
        g_numTiles = nt;
    }
}

__global__ void k_scatter(const int* __restrict__ labels) {
    int i = blockIdx.x * blockDim.x + threadIdx.x;
    if (i < BB) {
        int p = atomicAdd(&g_cursor[labels[i]], 1);
        g_perm[p] = i;
    }
}

// fp32 -> fp16 conversion (4 elems/thread)
__global__ void k_cvt(const float* __restrict__ in, __half* __restrict__ out, int n4) {
    int i = blockIdx.x * blockDim.x + threadIdx.x;
    if (i < n4) {
        float4 v = ((const float4*)in)[i];
        __half2* o = (__half2*)(out + (size_t)i * 4);
        o[0] = __floats2half2_rn(v.x, v.y);
        o[1] = __floats2half2_rn(v.z, v.w);
    }
}

// ---------------------------------------------------------------------------
__device__ __forceinline__ void mma16(float* c, const uint32_t* a, const uint32_t* b) {
    asm volatile(
        "mma.sync.aligned.m16n8k16.row.col.f32.f16.f16.f32 "
        "{%0,%1,%2,%3}, {%4,%5,%6,%7}, {%8,%9}, {%0,%1,%2,%3};\n"
        : "+f"(c[0]), "+f"(c[1]), "+f"(c[2]), "+f"(c[3])
        : "r"(a[0]), "r"(a[1]), "r"(a[2]), "r"(a[3]), "r"(b[0]), "r"(b[1]));
}
__device__ __forceinline__ void ldsm4(uint32_t* r, uint32_t saddr) {
    asm volatile("ldmatrix.sync.aligned.m8n8.x4.shared.b16 {%0,%1,%2,%3}, [%4];"
                 : "=r"(r[0]), "=r"(r[1]), "=r"(r[2]), "=r"(r[3]) : "r"(saddr));
}
__device__ __forceinline__ void ldsm4t(uint32_t* r, uint32_t saddr) {
    asm volatile("ldmatrix.sync.aligned.m8n8.x4.trans.shared.b16 {%0,%1,%2,%3}, [%4];"
                 : "=r"(r[0]), "=r"(r[1]), "=r"(r[2]), "=r"(r[3]) : "r"(saddr));
}
__device__ __forceinline__ void cp16(uint32_t saddr, const void* g, int szbytes) {
    asm volatile("cp.async.cg.shared.global [%0], [%1], 16, %2;\n"
                 :: "r"(saddr), "l"(g), "r"(szbytes));
}
#define CP_COMMIT() asm volatile("cp.async.commit_group;\n")
#define CP_WAIT1()  asm volatile("cp.async.wait_group 1;\n")
#define CP_WAIT0()  asm volatile("cp.async.wait_group 0;\n")

// smem (bytes): A[2][128][40]h, B[2][32][136]h
#define A_BUF 10240
#define B_BUF 8704
#define SB0   20480
#define SMEM_TOTAL 37888

// ---------------------------------------------------------------------------
// MODE 0: bias+relu -> fp16 Out.  MODE 3: bias only -> fp32 scatter Out.
// Tile 128x128x32, 8 warps 2(M)x4(N), warp 64x32.
// ---------------------------------------------------------------------------
template <int MODE, int K, int N>
__global__ void __launch_bounds__(256, 2)
k_hgemm(const __half* __restrict__ A, const __half* __restrict__ W,
        const float* __restrict__ bias, void* __restrict__ OutV,
        int unsharedF, int permAF) {
    if ((int)blockIdx.x >= g_numTiles) return;
    __shared__ __align__(16) __half smem_[SMEM_TOTAL / 2];
    uint32_t smb = (uint32_t)__cvta_generic_to_shared(smem_);

    int4 td = g_tiles[blockIdx.x];
    int rowStart = td.x, rows = td.y, cl = td.z;
    const __half* Wp = W + (unsharedF ? (size_t)cl * K * N : 0);
    const float* bp = bias + (unsharedF ? (size_t)cl * N : 0);
    int nb = blockIdx.y * 128;

    int tid = threadIdx.x;
    int warp = tid >> 5, lane = tid & 31;
    int wm = warp >> 2, wn = warp & 3;
    int g = lane >> 2, tg = lane & 3;

    // ---- staging coords: 2 A chunks + 2 B chunks of 16B per thread ----
    uint32_t aDst[2]; const __half* aSrc[2]; int aSz[2];
    uint32_t bDst[2]; const __half* bSrc[2];
#pragma unroll
    for (int i = 0; i < 2; i++) {
        int idx = tid + i * 256;            // 0..511
        int r = idx >> 2, ch = idx & 3;     // A: row, 16B chunk (8 halves)
        int ok = (r < rows);
        aSz[i] = ok ? 16 : 0;
        int ar = ok ? (permAF ? g_perm[rowStart + r] : rowStart + r) : 0;
        aDst[i] = smb + r * 80 + ch * 16;
        aSrc[i] = A + (size_t)ar * K + ch * 8;
        int kr = idx >> 4, cq = (idx & 15) << 3;   // B: k-row, n chunk
        bDst[i] = smb + SB0 + kr * 272 + cq * 2;
        bSrc[i] = Wp + (size_t)kr * N + nb + cq;
    }

    auto loadTile = [&](int blk, int b) {
        int ko = blk * 32;
#pragma unroll
        for (int i = 0; i < 2; i++) cp16(aDst[i] + b * A_BUF, aSrc[i] + ko, aSz[i]);
#pragma unroll
        for (int i = 0; i < 2; i++) cp16(bDst[i] + b * B_BUF, bSrc[i] + (size_t)ko * N, 16);
        CP_COMMIT();
    };

    // ---- fragment base addresses ----
    uint32_t aF = smb + (uint32_t)((wm * 64 + (lane & 15)) * 80 + ((lane >> 4) << 4));
    uint32_t bF = smb + SB0 +
        (uint32_t)((((lane >> 3) & 1) * 8 + (lane & 7)) * 272 + (wn * 32 + ((lane >> 4) << 3)) * 2);

    float acc[4][4][4];
#pragma unroll
    for (int a = 0; a < 4; a++)
#pragma unroll
        for (int b = 0; b < 4; b++)
#pragma unroll
            for (int d = 0; d < 4; d++) acc[a][b][d] = 0.f;

    const int nk = K / 32;
    loadTile(0, 0);
    if (nk > 1) loadTile(1, 1);

    for (int i = 0; i < nk; i++) {
        int b = i & 1;
        if (i + 2 <= nk) { CP_WAIT1(); } else { CP_WAIT0(); }
        __syncthreads();

        uint32_t aB = aF + b * A_BUF, bB = bF + b * B_BUF;
#pragma unroll
        for (int ks = 0; ks < 2; ks++) {
            uint32_t af[4][4], bfr[2][4];
#pragma unroll
            for (int mt = 0; mt < 4; mt++)
                ldsm4(af[mt], aB + mt * (16 * 80) + ks * 32);
#pragma unroll
            for (int np = 0; np < 2; np++)
                ldsm4t(bfr[np], bB + ks * (16 * 272) + np * 32);
#pragma unroll
            for (int mt = 0; mt < 4; mt++)
#pragma unroll
                for (int nt = 0; nt < 4; nt++)
                    mma16(acc[mt][nt], af[mt], &bfr[nt >> 1][(nt & 1) * 2]);
        }
        __syncthreads();
        if (i + 2 < nk) loadTile(i + 2, b);
    }

    // ---- epilogue ----
#pragma unroll
    for (int mt = 0; mt < 4; mt++) {
#pragma unroll
        for (int nt = 0; nt < 4; nt++) {
            int col = nb + wn * 32 + nt * 8 + 2 * tg;
            float bv0 = bp[col], bv1 = bp[col + 1];
#pragma unroll
            for (int h = 0; h < 2; h++) {
                int lr = wm * 64 + mt * 16 + g + h * 8;
                if (lr < rows) {
                    int grow = rowStart + lr;
                    float v0 = acc[mt][nt][2 * h + 0] + bv0;
                    float v1 = acc[mt][nt][2 * h + 1] + bv1;
                    if (MODE == 0) {
                        __half2 hv = __floats2half2_rn(fmaxf(v0, 0.f), fmaxf(v1, 0.f));
                        *(__half2*)((__half*)OutV + (size_t)grow * N + col) = hv;
                    } else {
                        int orig = g_perm[grow];
                        *(float2*)((float*)OutV + (size_t)orig * N + col) = make_float2(v0, v1);
                    }
                }
            }
        }
    }
}

// ---------------------------------------------------------------------------
// mu/lv dual-head + reparameterize. A fp16 [rows x 256]; B interleaved
// even col->mu, odd->lv (64 each). Sync staging; fp16 mma. Out fp16 [.,64].
// ---------------------------------------------------------------------------
__global__ void __launch_bounds__(256)
k_gemm_z(const __half* __restrict__ A, const float* __restrict__ W,
         const float* __restrict__ W2, const float* __restrict__ bias,
         const float* __restrict__ bias2, __half* __restrict__ Out,
         const float* __restrict__ epsp) {
    if ((int)blockIdx.x >= g_numTiles) return;
    const int K = 256;
    __shared__ __align__(16) __half As[128][40];
    __shared__ __align__(16) __half Bs[32][136];

    int4 td = g_tiles[blockIdx.x];
    int rowStart = td.x, rows = td.y;

    int tid = threadIdx.x;
    int warp = tid >> 5, lane = tid & 31;
    int wm = warp >> 2, wn = warp & 3;
    int g = lane >> 2, tg = lane & 3;

    uint32_t smbA = (uint32_t)__cvta_generic_to_shared(&As[0][0]);
    uint32_t smbB = (uint32_t)__cvta_generic_to_shared(&Bs[0][0]);
    uint32_t aF = smbA + (uint32_t)((wm * 64 + (lane & 15)) * 80 + ((lane >> 4) << 4));
    uint32_t bF = smbB +
        (uint32_t)((((lane >> 3) & 1) * 8 + (lane & 7)) * 272 + (wn * 32 + ((lane >> 4) << 3)) * 2);

    float acc[4][4][4];
#pragma unroll
    for (int a = 0; a < 4; a++)
#pragma unroll
        for (int b = 0; b < 4; b++)
#pragma unroll
            for (int d = 0; d < 4; d++) acc[a][b][d] = 0.f;

    for (int kb = 0; kb < K; kb += 32) {
#pragma unroll
        for (int i = 0; i < 2; i++) {
            int idx = tid + i * 256;
            int r = idx >> 2, ch = idx & 3;
            uint4 v = make_uint4(0, 0, 0, 0);
            if (r < rows)
                v = *(const uint4*)(A + (size_t)(rowStart + r) * K + kb + ch * 8);
            *(uint4*)&As[r][ch * 8] = v;
        }
        for (int idx = tid; idx < 32 * 128; idx += 256) {
            int kr = idx >> 7, n = idx & 127;
            const float* src = (n & 1) ? W2 : W;
            Bs[kr][n] = __float2half(src[(size_t)(kb + kr) * 64 + (n >> 1)]);
        }
        __syncthreads();
#pragma unroll
        for (int ks = 0; ks < 2; ks++) {
            uint32_t af[4][4], bfr[2][4];
#pragma unroll
            for (int mt = 0; mt < 4; mt++)
                ldsm4(af[mt], aF + mt * (16 * 80) + ks * 32);
#pragma unroll
            for (int np = 0; np < 2; np++)
                ldsm4t(bfr[np], bF + ks * (16 * 272) + np * 32);
#pragma unroll
            for (int mt = 0; mt < 4; mt++)
#pragma unroll
                for (int nt = 0; nt < 4; nt++)
                    mma16(acc[mt][nt], af[mt], &bfr[nt >> 1][(nt & 1) * 2]);
        }
        __syncthreads();
    }

#pragma unroll
    for (int mt = 0; mt < 4; mt++) {
#pragma unroll
        for (int nt = 0; nt < 4; nt++) {
            int j = wn * 16 + nt * 4 + tg;
            float bmu = bias[j], blv = bias2[j];
#pragma unroll
            for (int h = 0; h < 2; h++) {
                int lr = wm * 64 + mt * 16 + g + h * 8;
                if (lr < rows) {
                    int grow = rowStart + lr;
                    int orig = g_perm[grow];
                    float mu = acc[mt][nt][2 * h + 0] + bmu;
                    float lv = acc[mt][nt][2 * h + 1] + blv;
                    float e = epsp[(size_t)orig * 64 + j];
                    Out[(size_t)grow * 64 + j] = __float2half(mu + expf(0.5f * lv) * e);
                }
            }
        }
    }
}

// ---------------------------------------------------------------------------
extern "C" void kernel_launch(void* const* d_in, const int* in_sizes, int n_in,
                              void* d_out, int out_size) {
    const float* x      = (const float*)d_in[0];
    const int*   lbl    = (const int*)d_in[1];
    const float* eps    = (const float*)d_in[2];
    const float* enc_W0 = (const float*)d_in[3];
    const float* enc_b0 = (const float*)d_in[4];
    const float* enc_Wu = (const float*)d_in[5];
    const float* enc_bu = (const float*)d_in[6];
    const float* enc_W2 = (const float*)d_in[7];
    const float* enc_b2 = (const float*)d_in[8];
    const float* mu_W   = (const float*)d_in[9];
    const float* mu_b   = (const float*)d_in[10];
    const float* lv_W   = (const float*)d_in[11];
    const float* lv_b   = (const float*)d_in[12];
    const float* dWu0   = (const float*)d_in[13];
    const float* dbu0   = (const float*)d_in[14];
    const float* dW1    = (const float*)d_in[15];
    const float* db1    = (const float*)d_in[16];
    const float* dWu2   = (const float*)d_in[17];
    const float* dbu2   = (const float*)d_in[18];
    const float* fW     = (const float*)d_in[19];
    const float* fb     = (const float*)d_in[20];
    float* out = (float*)d_out;

    __half *bufA, *bufB, *xh, *wh;
    cudaGetSymbolAddress((void**)&bufA, g_bufA);
    cudaGetSymbolAddress((void**)&bufB, g_bufB);
    cudaGetSymbolAddress((void**)&xh,   g_xh);
    cudaGetSymbolAddress((void**)&wh,   g_wh);

    k_setup<<<1, 256>>>(lbl);
    k_scatter<<<64, 256>>>(lbl);

    // pre-convert x + mainloop weights to fp16
    k_cvt<<<(BB * 512 / 4 + 255) / 256, 256>>>(x, xh, BB * 512 / 4);
    k_cvt<<<(524288 / 4 + 255) / 256, 256>>>(enc_W0, wh + O_EW0, 524288 / 4);
    k_cvt<<<(4194304 / 4 + 255) / 256, 256>>>(enc_Wu, wh + O_EWU, 4194304 / 4);
    k_cvt<<<(131072 / 4 + 255) / 256, 256>>>(enc_W2, wh + O_EW2, 131072 / 4);
    k_cvt<<<(131072 / 4 + 255) / 256, 256>>>(dWu0, wh + O_DWU0, 131072 / 4);
    k_cvt<<<(131072 / 4 + 255) / 256, 256>>>(dW1, wh + O_DW1, 131072 / 4);
    k_cvt<<<(4194304 / 4 + 255) / 256, 256>>>(dWu2, wh + O_DWU2, 4194304 / 4);
    k_cvt<<<(4194304 / 4 + 255) / 256, 256>>>(fW, wh + O_FW, 4194304 / 4);

    // L1: xh(perm) @ enc_W0 [512->1024] relu
    k_hgemm<0, 512, 1024><<<dim3(MAXT, 8), 256>>>(xh, wh + O_EW0, enc_b0, bufA, 0, 1);
    // L2: H1 @ enc_Wu[c] [1024->512] relu
    k_hgemm<0, 1024, 512><<<dim3(MAXT, 4), 256>>>(bufA, wh + O_EWU, enc_bu, bufB, 1, 0);
    // L3: H2 @ enc_W2 [512->256] relu
    k_hgemm<0, 512, 256><<<dim3(MAXT, 2), 256>>>(bufB, wh + O_EW2, enc_b2, bufA, 0, 0);
    // L4: mu/lv heads + reparameterize -> Z (fp16)
    k_gemm_z<<<dim3(MAXT, 1), 256>>>(bufA, mu_W, lv_W, mu_b, lv_b, bufB, eps);
    // L5: Z @ dec_Wu0[c] [64->256] relu
    k_hgemm<0, 64, 256><<<dim3(MAXT, 2), 256>>>(bufB, wh + O_DWU0, dbu0, bufA, 1, 0);
    // L6: D1 @ dec_W1 [256->512] relu
    k_hgemm<0, 256, 512><<<dim3(MAXT, 4), 256>>>(bufA, wh + O_DW1, db1, bufB, 0, 0);
    // L7: D2 @ dec_Wu2[c] [512->1024] relu
    k_hgemm<0, 512, 1024><<<dim3(MAXT, 8), 256>>>(bufB, wh + O_DWU2, dbu2, bufA, 1, 0);
    // L8: D3 @ fin_W[c] [1024->512], scatter to original rows (fp32 out)
    k_hgemm<3, 1024, 512><<<dim3(MAXT, 4), 256>>>(bufA, wh + O_FW, fb, out, 1, 0);
}

// round 6
// speedup vs baseline: 2.0206x; 1.1409x over previous
#include <cuda_runtime.h>
#include <cuda_fp16.h>
#include <cstdint>

// ============================================================================
// CISSVAE forward on GB300 — R6: fp16 m16n8k16, 3-stage cp.async pipeline
// (single barrier per k-block), fused one-launch fp32->fp16 prepass.
// Rows counting-sorted by cluster -> per-cluster layers are dense segments.
// ============================================================================

#define BB 16384
#define NC 8
#define MAXT 136

__device__ __half g_bufA[BB * 1024];
__device__ __half g_bufB[BB * 1024];
__device__ __half g_xh[BB * 512];
__device__ __half g_wh[13500416];
__device__ int    g_perm[BB];
__device__ int    g_cursor[NC];
__device__ int4   g_tiles[MAXT];
__device__ int    g_numTiles;

#define O_EW0   0
#define O_EWU   524288
#define O_EW2   4718592
#define O_DWU0  4849664
#define O_DW1   4980736
#define O_DWU2  5111808
#define O_FW    9306112

// ---------------------------------------------------------------------------
__global__ void k_setup(const int* __restrict__ labels) {
    __shared__ int cnt[NC];
    int t = threadIdx.x;
    if (t < NC) cnt[t] = 0;
    __syncthreads();
    int loc[NC];
#pragma unroll
    for (int c = 0; c < NC; c++) loc[c] = 0;
    for (int i = t; i < BB; i += blockDim.x) {
        int v = labels[i];
#pragma unroll
        for (int c = 0; c < NC; c++) loc[c] += (v == c);
    }
#pragma unroll
    for (int c = 0; c < NC; c++)
        if (loc[c]) atomicAdd(&cnt[c], loc[c]);
    __syncthreads();
    if (t == 0) {
        int start = 0, nt = 0;
        for (int c = 0; c < NC; c++) {
            g_cursor[c] = start;
            int n = cnt[c];
            for (int off = 0; off < n; off += 128) {
                g_tiles[nt] = make_int4(start + off, min(128, n - off), c, 0);
                nt++;
            }
            start += n;
        }
        g_numTiles = nt;
    }
}

__global__ void k_scatter(const int* __restrict__ labels) {
    int i = blockIdx.x * blockDim.x + threadIdx.x;
    if (i < BB) {
        int p = atomicAdd(&g_cursor[labels[i]], 1);
        g_perm[p] = i;
    }
}

// ---------------------------------------------------------------------------
// Fused fp32->fp16 conversion: all tensors in ONE launch.
// Each block handles 1024 float4 (4096 floats) of its job.
// ---------------------------------------------------------------------------
#define NJOBS 8
struct CvtJobs {
    const float* s[NJOBS];
    __half* d[NJOBS];
    int n4[NJOBS];
    int bstart[NJOBS + 1];
};

__global__ void __launch_bounds__(256)
k_cvt_all(CvtJobs J) {
    int b = blockIdx.x;
    int j = 0;
#pragma unroll
    for (int q = 1; q < NJOBS; q++)
        if (b >= J.bstart[q]) j = q;
    int lb = b - J.bstart[j];
    const float4* src = (const float4*)J.s[j];
    __half2* dst = (__half2*)J.d[j];
    int n4 = J.n4[j];
#pragma unroll
    for (int it = 0; it < 4; it++) {
        int idx = lb * 1024 + it * 256 + threadIdx.x;
        if (idx < n4) {
            float4 v = src[idx];
            dst[idx * 2 + 0] = __floats2half2_rn(v.x, v.y);
            dst[idx * 2 + 1] = __floats2half2_rn(v.z, v.w);
        }
    }
}

// ---------------------------------------------------------------------------
__device__ __forceinline__ void mma16(float* c, const uint32_t* a, const uint32_t* b) {
    asm volatile(
        "mma.sync.aligned.m16n8k16.row.col.f32.f16.f16.f32 "
        "{%0,%1,%2,%3}, {%4,%5,%6,%7}, {%8,%9}, {%0,%1,%2,%3};\n"
        : "+f"(c[0]), "+f"(c[1]), "+f"(c[2]), "+f"(c[3])
        : "r"(a[0]), "r"(a[1]), "r"(a[2]), "r"(a[3]), "r"(b[0]), "r"(b[1]));
}
__device__ __forceinline__ void ldsm4(uint32_t* r, uint32_t saddr) {
    asm volatile("ldmatrix.sync.aligned.m8n8.x4.shared.b16 {%0,%1,%2,%3}, [%4];"
                 : "=r"(r[0]), "=r"(r[1]), "=r"(r[2]), "=r"(r[3]) : "r"(saddr));
}
__device__ __forceinline__ void ldsm4t(uint32_t* r, uint32_t saddr) {
    asm volatile("ldmatrix.sync.aligned.m8n8.x4.trans.shared.b16 {%0,%1,%2,%3}, [%4];"
                 : "=r"(r[0]), "=r"(r[1]), "=r"(r[2]), "=r"(r[3]) : "r"(saddr));
}
__device__ __forceinline__ void cp16(uint32_t saddr, const void* g, int szbytes) {
    asm volatile("cp.async.cg.shared.global [%0], [%1], 16, %2;\n"
                 :: "r"(saddr), "l"(g), "r"(szbytes));
}
#define CP_COMMIT() asm volatile("cp.async.commit_group;\n")
#define CP_WAIT1()  asm volatile("cp.async.wait_group 1;\n")
#define CP_WAIT0()  asm volatile("cp.async.wait_group 0;\n")

// smem: 3 stages, A[128][80B] + B[32][272B] each
#define A_BUF 10240
#define B_BUF 8704
#define SB0   30720           // 3*A_BUF
#define SMEM_TOTAL 56832      // SB0 + 3*B_BUF

// ---------------------------------------------------------------------------
// MODE 0: bias+relu -> fp16 Out.  MODE 3: bias only -> fp32 scatter Out.
// Tile 128x128x32, 8 warps 2(M)x4(N), warp 64x32. 3-stage pipeline.
// ---------------------------------------------------------------------------
template <int MODE, int K, int N>
__global__ void __launch_bounds__(256, 2)
k_hgemm(const __half* __restrict__ A, const __half* __restrict__ W,
        const float* __restrict__ bias, void* __restrict__ OutV,
        int unsharedF, int permAF) {
    if ((int)blockIdx.x >= g_numTiles) return;
    __shared__ __align__(16) __half smem_[SMEM_TOTAL / 2];
    uint32_t smb = (uint32_t)__cvta_generic_to_shared(smem_);

    int4 td = g_tiles[blockIdx.x];
    int rowStart = td.x, rows = td.y, cl = td.z;
    const __half* Wp = W + (unsharedF ? (size_t)cl * K * N : 0);
    const float* bp = bias + (unsharedF ? (size_t)cl * N : 0);
    int nb = blockIdx.y * 128;

    int tid = threadIdx.x;
    int warp = tid >> 5, lane = tid & 31;
    int wm = warp >> 2, wn = warp & 3;
    int g = lane >> 2, tg = lane & 3;

    // staging coords: 2 A + 2 B 16B chunks per thread
    uint32_t aDst[2]; const __half* aSrc[2]; int aSz[2];
    uint32_t bDst[2]; const __half* bSrc[2];
#pragma unroll
    for (int i = 0; i < 2; i++) {
        int idx = tid + i * 256;
        int r = idx >> 2, ch = idx & 3;
        int ok = (r < rows);
        aSz[i] = ok ? 16 : 0;
        int ar = ok ? (permAF ? g_perm[rowStart + r] : rowStart + r) : 0;
        aDst[i] = smb + r * 80 + ch * 16;
        aSrc[i] = A + (size_t)ar * K + ch * 8;
        int kr = idx >> 4, cq = (idx & 15) << 3;
        bDst[i] = smb + SB0 + kr * 272 + cq * 2;
        bSrc[i] = Wp + (size_t)kr * N + nb + cq;
    }

    auto loadTile = [&](int blk, int s) {
        int ko = blk * 32;
#pragma unroll
        for (int i = 0; i < 2; i++) cp16(aDst[i] + s * A_BUF, aSrc[i] + ko, aSz[i]);
#pragma unroll
        for (int i = 0; i < 2; i++) cp16(bDst[i] + s * B_BUF, bSrc[i] + (size_t)ko * N, 16);
        CP_COMMIT();
    };

    uint32_t aF = smb + (uint32_t)((wm * 64 + (lane & 15)) * 80 + ((lane >> 4) << 4));
    uint32_t bF = smb + SB0 +
        (uint32_t)((((lane >> 3) & 1) * 8 + (lane & 7)) * 272 + (wn * 32 + ((lane >> 4) << 3)) * 2);

    float acc[4][4][4];
#pragma unroll
    for (int a = 0; a < 4; a++)
#pragma unroll
        for (int b = 0; b < 4; b++)
#pragma unroll
            for (int d = 0; d < 4; d++) acc[a][b][d] = 0.f;

    const int nk = K / 32;
    loadTile(0, 0);
    if (nk > 1) loadTile(1, 1);

    for (int i = 0; i < nk; i++) {
        int s = i % 3;
        int rem = nk - 1 - i;
        if (rem >= 1) { CP_WAIT1(); } else { CP_WAIT0(); }
        __syncthreads();
        if (i + 2 < nk) loadTile(i + 2, (i + 2) % 3);   // after barrier: safe overwrite

        uint32_t aB = aF + s * A_BUF, bB = bF + s * B_BUF;
#pragma unroll
        for (int ks = 0; ks < 2; ks++) {
            uint32_t af[4][4], bfr[2][4];
#pragma unroll
            for (int mt = 0; mt < 4; mt++)
                ldsm4(af[mt], aB + mt * (16 * 80) + ks * 32);
#pragma unroll
            for (int np = 0; np < 2; np++)
                ldsm4t(bfr[np], bB + ks * (16 * 272) + np * 32);
#pragma unroll
            for (int mt = 0; mt < 4; mt++)
#pragma unroll
                for (int nt = 0; nt < 4; nt++)
                    mma16(acc[mt][nt], af[mt], &bfr[nt >> 1][(nt & 1) * 2]);
        }
    }

    // epilogue
#pragma unroll
    for (int mt = 0; mt < 4; mt++) {
#pragma unroll
        for (int nt = 0; nt < 4; nt++) {
            int col = nb + wn * 32 + nt * 8 + 2 * tg;
            float bv0 = bp[col], bv1 = bp[col + 1];
#pragma unroll
            for (int h = 0; h < 2; h++) {
                int lr = wm * 64 + mt * 16 + g + h * 8;
                if (lr < rows) {
                    int grow = rowStart + lr;
                    float v0 = acc[mt][nt][2 * h + 0] + bv0;
                    float v1 = acc[mt][nt][2 * h + 1] + bv1;
                    if (MODE == 0) {
                        __half2 hv = __floats2half2_rn(fmaxf(v0, 0.f), fmaxf(v1, 0.f));
                        *(__half2*)((__half*)OutV + (size_t)grow * N + col) = hv;
                    } else {
                        int orig = g_perm[grow];
                        *(float2*)((float*)OutV + (size_t)orig * N + col) = make_float2(v0, v1);
                    }
                }
            }
        }
    }
}

// ---------------------------------------------------------------------------
// mu/lv dual-head + reparameterize (interleaved B: even col->mu, odd->lv).
// ---------------------------------------------------------------------------
__global__ void __launch_bounds__(256)
k_gemm_z(const __half* __restrict__ A, const float* __restrict__ W,
         const float* __restrict__ W2, const float* __restrict__ bias,
         const float* __restrict__ bias2, __half* __restrict__ Out,
         const float* __restrict__ epsp) {
    if ((int)blockIdx.x >= g_numTiles) return;
    const int K = 256;
    __shared__ __align__(16) __half As[128][40];
    __shared__ __align__(16) __half Bs[32][136];

    int4 td = g_tiles[blockIdx.x];
    int rowStart = td.x, rows = td.y;

    int tid = threadIdx.x;
    int warp = tid >> 5, lane = tid & 31;
    int wm = warp >> 2, wn = warp & 3;
    int g = lane >> 2, tg = lane & 3;

    uint32_t smbA = (uint32_t)__cvta_generic_to_shared(&As[0][0]);
    uint32_t smbB = (uint32_t)__cvta_generic_to_shared(&Bs[0][0]);
    uint32_t aF = smbA + (uint32_t)((wm * 64 + (lane & 15)) * 80 + ((lane >> 4) << 4));
    uint32_t bF = smbB +
        (uint32_t)((((lane >> 3) & 1) * 8 + (lane & 7)) * 272 + (wn * 32 + ((lane >> 4) << 3)) * 2);

    float acc[4][4][4];
#pragma unroll
    for (int a = 0; a < 4; a++)
#pragma unroll
        for (int b = 0; b < 4; b++)
#pragma unroll
            for (int d = 0; d < 4; d++) acc[a][b][d] = 0.f;

    for (int kb = 0; kb < K; kb += 32) {
#pragma unroll
        for (int i = 0; i < 2; i++) {
            int idx = tid + i * 256;
            int r = idx >> 2, ch = idx & 3;
            uint4 v = make_uint4(0, 0, 0, 0);
            if (r < rows)
                v = *(const uint4*)(A + (size_t)(rowStart + r) * K + kb + ch * 8);
            *(uint4*)&As[r][ch * 8] = v;
        }
        for (int idx = tid; idx < 32 * 128; idx += 256) {
            int kr = idx >> 7, n = idx & 127;
            const float* src = (n & 1) ? W2 : W;
            Bs[kr][n] = __float2half(src[(size_t)(kb + kr) * 64 + (n >> 1)]);
        }
        __syncthreads();
#pragma unroll
        for (int ks = 0; ks < 2; ks++) {
            uint32_t af[4][4], bfr[2][4];
#pragma unroll
            for (int mt = 0; mt < 4; mt++)
                ldsm4(af[mt], aF + mt * (16 * 80) + ks * 32);
#pragma unroll
            for (int np = 0; np < 2; np++)
                ldsm4t(bfr[np], bF + ks * (16 * 272) + np * 32);
#pragma unroll
            for (int mt = 0; mt < 4; mt++)
#pragma unroll
                for (int nt = 0; nt < 4; nt++)
                    mma16(acc[mt][nt], af[mt], &bfr[nt >> 1][(nt & 1) * 2]);
        }
        __syncthreads();
    }

#pragma unroll
    for (int mt = 0; mt < 4; mt++) {
#pragma unroll
        for (int nt = 0; nt < 4; nt++) {
            int j = wn * 16 + nt * 4 + tg;
            float bmu = bias[j], blv = bias2[j];
#pragma unroll
            for (int h = 0; h < 2; h++) {
                int lr = wm * 64 + mt * 16 + g + h * 8;
                if (lr < rows) {
                    int grow = rowStart + lr;
                    int orig = g_perm[grow];
                    float mu = acc[mt][nt][2 * h + 0] + bmu;
                    float lv = acc[mt][nt][2 * h + 1] + blv;
                    float e = epsp[(size_t)orig * 64 + j];
                    Out[(size_t)grow * 64 + j] = __float2half(mu + expf(0.5f * lv) * e);
                }
            }
        }
    }
}

// ---------------------------------------------------------------------------
extern "C" void kernel_launch(void* const* d_in, const int* in_sizes, int n_in,
                              void* d_out, int out_size) {
    const float* x      = (const float*)d_in[0];
    const int*   lbl    = (const int*)d_in[1];
    const float* eps    = (const float*)d_in[2];
    const float* enc_W0 = (const float*)d_in[3];
    const float* enc_b0 = (const float*)d_in[4];
    const float* enc_Wu = (const float*)d_in[5];
    const float* enc_bu = (const float*)d_in[6];
    const float* enc_W2 = (const float*)d_in[7];
    const float* enc_b2 = (const float*)d_in[8];
    const float* mu_W   = (const float*)d_in[9];
    const float* mu_b   = (const float*)d_in[10];
    const float* lv_W   = (const float*)d_in[11];
    const float* lv_b   = (const float*)d_in[12];
    const float* dWu0   = (const float*)d_in[13];
    const float* dbu0   = (const float*)d_in[14];
    const float* dW1    = (const float*)d_in[15];
    const float* db1    = (const float*)d_in[16];
    const float* dWu2   = (const float*)d_in[17];
    const float* dbu2   = (const float*)d_in[18];
    const float* fW     = (const float*)d_in[19];
    const float* fb     = (const float*)d_in[20];
    float* out = (float*)d_out;

    __half *bufA, *bufB, *xh, *wh;
    cudaGetSymbolAddress((void**)&bufA, g_bufA);
    cudaGetSymbolAddress((void**)&bufB, g_bufB);
    cudaGetSymbolAddress((void**)&xh,   g_xh);
    cudaGetSymbolAddress((void**)&wh,   g_wh);

    k_setup<<<1, 256>>>(lbl);
    k_scatter<<<64, 256>>>(lbl);

    // fused fp32->fp16 prepass (x + all 7 mainloop weights), one launch
    {
        CvtJobs J;
        const float* srcs[NJOBS] = {x, enc_W0, enc_Wu, enc_W2, dWu0, dW1, dWu2, fW};
        __half* dsts[NJOBS] = {xh, wh + O_EW0, wh + O_EWU, wh + O_EW2,
                               wh + O_DWU0, wh + O_DW1, wh + O_DWU2, wh + O_FW};
        int n4s[NJOBS] = {BB * 512 / 4, 524288 / 4, 4194304 / 4, 131072 / 4,
                          131072 / 4, 131072 / 4, 4194304 / 4, 4194304 / 4};
        int bs = 0;
        for (int j = 0; j < NJOBS; j++) {
            J.s[j] = srcs[j]; J.d[j] = dsts[j]; J.n4[j] = n4s[j];
            J.bstart[j] = bs;
            bs += (n4s[j] + 1023) / 1024;
        }
        J.bstart[NJOBS] = bs;
        k_cvt_all<<<bs, 256>>>(J);
    }

    // L1: xh(perm) @ enc_W0 [512->1024] relu
    k_hgemm<0, 512, 1024><<<dim3(MAXT, 8), 256>>>(xh, wh + O_EW0, enc_b0, bufA, 0, 1);
    // L2: H1 @ enc_Wu[c] [1024->512] relu
    k_hgemm<0, 1024, 512><<<dim3(MAXT, 4), 256>>>(bufA, wh + O_EWU, enc_bu, bufB, 1, 0);
    // L3: H2 @ enc_W2 [512->256] relu
    k_hgemm<0, 512, 256><<<dim3(MAXT, 2), 256>>>(bufB, wh + O_EW2, enc_b2, bufA, 0, 0);
    // L4: mu/lv heads + reparameterize -> Z (fp16)
    k_gemm_z<<<dim3(MAXT, 1), 256>>>(bufA, mu_W, lv_W, mu_b, lv_b, bufB, eps);
    // L5: Z @ dec_Wu0[c] [64->256] relu
    k_hgemm<0, 64, 256><<<dim3(MAXT, 2), 256>>>(bufB, wh + O_DWU0, dbu0, bufA, 1, 0);
    // L6: D1 @ dec_W1 [256->512] relu
    k_hgemm<0, 256, 512><<<dim3(MAXT, 4), 256>>>(bufA, wh + O_DW1, db1, bufB, 0, 0);
    // L7: D2 @ dec_Wu2[c] [512->1024] relu
    k_hgemm<0, 512, 1024><<<dim3(MAXT, 8), 256>>>(bufB, wh + O_DWU2, dbu2, bufA, 1, 0);
    // L8: D3 @ fin_W[c] [1024->512], scatter to original rows (fp32 out)
    k_hgemm<3, 1024, 512><<<dim3(MAXT, 4), 256>>>(bufA, wh + O_FW, fb, out, 1, 0);
}